// round 8
// baseline (speedup 1.0000x reference)
#include <cuda_runtime.h>
#include <math.h>

#define NPIX 16384          // 128*128
#define BATCH 2

// ---------------- scratch (static device memory; no allocations) ----------------
__device__ float g_lf0 [BATCH*128*NPIX];   // NCHW
__device__ float g_lf1 [BATCH*128*NPIX];   // NCHW
__device__ float g_lf0t[BATCH*NPIX*128];   // NHWC
__device__ float g_lf1t[BATCH*NPIX*128];   // NHWC
__device__ float g_tmp [BATCH*128*NPIX];
__device__ float g_at  [BATCH*NPIX*128];   // a, NHWC
__device__ float g_gt  [BATCH*NPIX*128];   // g = M·a, NHWC
__device__ float g_alpha[BATCH*NPIX];
__device__ float g_beta [BATCH*NPIX];
__device__ float g_flow[BATCH*2*NPIX];
__device__ float g_fi  [BATCH*2*NPIX];
__device__ float g_hcat[BATCH*264*NPIX];   // 258 real channels zero-padded to 264
__device__ float g_h2  [BATCH*64*NPIX];
__device__ float g_Mw  [128*128];          // M[i][j] = sum_d qw[d,i]*kw[d,j]
__device__ float g_uvc [260];              // u[0..127], v[128..255], c at [256]

__device__ __forceinline__ float gelu_f(float x) {
    return 0.5f * x * (1.0f + erff(x * 0.7071067811865476f));
}

// ---------------- 3x3 conv: tile 32x16 px, 16 co per block ----------------
// thread: 4 output channels x (2 wide x 4 tall pixel quad) = 32 accumulators.
// Per-ci: 288 FMA vs 240B LDS -> FMA-bound (was 144 FMA vs 208B -> LDS-bound).
template<int ACT>   // 0=none, 1=gelu
__global__ void __launch_bounds__(256, 2) conv3x3_kernel(
    const float* __restrict__ in, const float* __restrict__ w,
    const float* __restrict__ bias, float* __restrict__ out,
    int Cin, int CinPad, int Cout)
{
    __shared__ float in_s[8][18][36];
    __shared__ float w_s[8][9][16];

    const int tid = threadIdx.x;
    const int tile = blockIdx.x;        // 0..31: 4 x-tiles, 8 y-tiles
    const int tx0 = (tile & 3) * 32;
    const int ty0 = (tile >> 2) * 16;
    const int cog = blockIdx.y * 16;
    const int b   = blockIdx.z;
    const int cg  = tid >> 6;           // 0..3 -> co = cog + cg*4 .. +3
    const int p   = tid & 63;
    const int qx  = (p & 15) * 2;       // 0..30
    const int qy  = (p >> 4) * 4;       // 0..12

    float acc[4][4][2];                 // [co][dy(4)][dx(2)]
    #pragma unroll
    for (int i = 0; i < 4; i++)
        #pragma unroll
        for (int dy = 0; dy < 4; dy++)
            #pragma unroll
            for (int dx = 0; dx < 2; dx++) acc[i][dy][dx] = 0.f;

    const int nchunk = CinPad >> 3;
    for (int ch = 0; ch < nchunk; ch++) {
        const int ci0 = ch * 8;
        // input halo tile: 8ch x 18 x 34
        for (int idx = tid; idx < 8 * 18 * 34; idx += 256) {
            int ci = idx / 612;
            int rem = idx - ci * 612;
            int r = rem / 34;
            int c = rem - r * 34;
            int gy = ty0 - 1 + r, gx = tx0 - 1 + c;
            float v = 0.f;
            if ((unsigned)gy < 128u && (unsigned)gx < 128u)
                v = in[((b * CinPad + ci0 + ci) << 14) + (gy << 7) + gx];
            in_s[ci][r][c] = v;
        }
        // weights: 8ci x 9 x 16co
        for (int idx = tid; idx < 8 * 9 * 16; idx += 256) {
            int col = idx & 15;
            int rem = idx >> 4;
            int k = rem % 9;
            int ci = rem / 9;
            int cig = ci0 + ci;
            float v = (cig < Cin) ? w[((cog + col) * Cin + cig) * 9 + k] : 0.f;
            w_s[ci][k][col] = v;
        }
        __syncthreads();
        #pragma unroll
        for (int ci = 0; ci < 8; ci++) {
            float v[6][4];
            #pragma unroll
            for (int r = 0; r < 6; r++) {
                float2 a0 = *(const float2*)&in_s[ci][qy + r][qx];
                float2 a1 = *(const float2*)&in_s[ci][qy + r][qx + 2];
                v[r][0] = a0.x; v[r][1] = a0.y; v[r][2] = a1.x; v[r][3] = a1.y;
            }
            #pragma unroll
            for (int k = 0; k < 9; k++) {
                const int ky = k / 3, kx = k % 3;
                float4 wv = *(const float4*)&w_s[ci][k][cg * 4];
                #pragma unroll
                for (int dy = 0; dy < 4; dy++)
                    #pragma unroll
                    for (int dx = 0; dx < 2; dx++) {
                        float iv = v[ky + dy][kx + dx];
                        acc[0][dy][dx] += wv.x * iv;
                        acc[1][dy][dx] += wv.y * iv;
                        acc[2][dy][dx] += wv.z * iv;
                        acc[3][dy][dx] += wv.w * iv;
                    }
            }
        }
        __syncthreads();
    }
    #pragma unroll
    for (int i = 0; i < 4; i++) {
        int co = cog + cg * 4 + i;
        float bv = bias[co];
        #pragma unroll
        for (int dy = 0; dy < 4; dy++)
            #pragma unroll
            for (int dx = 0; dx < 2; dx++) {
                float r = acc[i][dy][dx] + bv;
                if (ACT == 1) r = gelu_f(r);
                out[((b * Cout + co) << 14) + ((ty0 + qy + dy) << 7) + (tx0 + qx + dx)] = r;
            }
    }
}

// ---------------- NCHW [128][NPIX] -> NHWC [NPIX][128] transpose ----------------
__global__ void __launch_bounds__(256) transpose_kernel(
    const float* __restrict__ in, float* __restrict__ out)
{
    __shared__ float t[32][33];
    const int b  = blockIdx.z;
    const int p0 = blockIdx.x * 32;
    const int c0 = blockIdx.y * 32;
    const int x  = threadIdx.x & 31;
    const int yy = threadIdx.x >> 5;
    #pragma unroll
    for (int i = 0; i < 4; i++)
        t[yy + i * 8][x] = in[(b * 128 + c0 + yy + i * 8) * NPIX + p0 + x];
    __syncthreads();
    #pragma unroll
    for (int i = 0; i < 4; i++)
        out[(b * NPIX + p0 + yy + i * 8) * 128 + c0 + x] = t[x][yy + i * 8];
}

// ---------------- prep: M[i][j] = sum_d qw[d*128+i]*kw[d*128+j] ----------------
__global__ void __launch_bounds__(256) prep_M_kernel(
    const float* __restrict__ qw, const float* __restrict__ kw, float* __restrict__ Mw)
{
    int t = blockIdx.x * 256 + threadIdx.x;     // 64 blocks -> 16384
    int i = t >> 7, j = t & 127;
    float s = 0.f;
    for (int d = 0; d < 128; d++)
        s += qw[d * 128 + i] * kw[d * 128 + j];
    Mw[i * 128 + j] = s;
}

__global__ void prep_uvc_kernel(
    const float* __restrict__ qw, const float* __restrict__ qb,
    const float* __restrict__ kw, const float* __restrict__ kb,
    float* __restrict__ uvc)
{
    int j = threadIdx.x;   // 128 threads
    float u = 0.f, v = 0.f;
    for (int d = 0; d < 128; d++) {
        u += qb[d] * kw[d * 128 + j];
        v += qw[d * 128 + j] * kb[d];
    }
    uvc[j] = u;
    uvc[128 + j] = v;
    if (j == 0) {
        float c = 0.f;
        for (int d = 0; d < 128; d++) c += qb[d] * kb[d];
        uvc[256] = c;
    }
}

// ---------------- bilinear setup ----------------
struct Bilin { int i00, i01, i10, i11; float w00, w01, w10, w11; };
__device__ __forceinline__ Bilin bilin_setup(float fx, float fy, int x, int y) {
    float xf = fminf(fmaxf((float)x + fx, 0.f), 127.f);
    float yf = fminf(fmaxf((float)y + fy, 0.f), 127.f);
    float x0f = floorf(xf), y0f = floorf(yf);
    int x0 = (int)x0f, y0 = (int)y0f;
    int x1 = min(x0 + 1, 127), y1 = min(y0 + 1, 127);
    float wx = xf - x0f, wy = yf - y0f;
    Bilin r;
    r.i00 = y0 * 128 + x0; r.i01 = y0 * 128 + x1;
    r.i10 = y1 * 128 + x0; r.i11 = y1 * 128 + x1;
    r.w00 = (1.f - wx) * (1.f - wy); r.w01 = wx * (1.f - wy);
    r.w10 = (1.f - wx) * wy;         r.w11 = wx * wy;
    return r;
}

// ---------------- warp+diff+norm, NHWC, also emits alpha/beta -------------------
__global__ void __launch_bounds__(256) warp_diff_t_kernel(
    const float* __restrict__ lf0t, const float* __restrict__ lf1t,
    const float* __restrict__ flow, const float* __restrict__ uvc,
    float* __restrict__ at, float* __restrict__ alpha, float* __restrict__ beta)
{
    const int warpId = threadIdx.x >> 5;
    const int lane   = threadIdx.x & 31;
    const int pid = blockIdx.x * 8 + warpId;
    const int b = pid >> 14;
    const int rem = pid & 16383;
    const int y = rem >> 7, x = rem & 127;

    float fx = flow[(b * 2 + 0) * NPIX + rem];
    float fy = flow[(b * 2 + 1) * NPIX + rem];
    Bilin bl = bilin_setup(fx, fy, x, y);

    const float* l1 = lf1t + (size_t)(b * NPIX) * 128 + lane * 4;
    float4 f00 = *(const float4*)&l1[bl.i00 * 128];
    float4 f01 = *(const float4*)&l1[bl.i01 * 128];
    float4 f10 = *(const float4*)&l1[bl.i10 * 128];
    float4 f11 = *(const float4*)&l1[bl.i11 * 128];
    float4 x0 = *(const float4*)&lf0t[(size_t)(b * NPIX + rem) * 128 + lane * 4];

    float4 d;
    d.x = x0.x - (f00.x * bl.w00 + f01.x * bl.w01 + f10.x * bl.w10 + f11.x * bl.w11);
    d.y = x0.y - (f00.y * bl.w00 + f01.y * bl.w01 + f10.y * bl.w10 + f11.y * bl.w11);
    d.z = x0.z - (f00.z * bl.w00 + f01.z * bl.w01 + f10.z * bl.w10 + f11.z * bl.w11);
    d.w = x0.w - (f00.w * bl.w00 + f01.w * bl.w01 + f10.w * bl.w10 + f11.w * bl.w11);

    float ss = d.x * d.x + d.y * d.y + d.z * d.z + d.w * d.w;
    #pragma unroll
    for (int o = 16; o > 0; o >>= 1) ss += __shfl_xor_sync(0xffffffffu, ss, o);
    float inv = 1.f / fmaxf(sqrtf(ss), 1e-12f);

    float4 a4;
    a4.x = 1.f - d.x * inv; a4.y = 1.f - d.y * inv;
    a4.z = 1.f - d.z * inv; a4.w = 1.f - d.w * inv;
    *(float4*)&at[(size_t)(b * NPIX + rem) * 128 + lane * 4] = a4;

    float4 u4 = *(const float4*)&uvc[lane * 4];
    float4 v4 = *(const float4*)&uvc[128 + lane * 4];
    float pa = u4.x * a4.x + u4.y * a4.y + u4.z * a4.z + u4.w * a4.w;
    float pb = v4.x * a4.x + v4.y * a4.y + v4.z * a4.z + v4.w * a4.w;
    #pragma unroll
    for (int o = 16; o > 0; o >>= 1) {
        pa += __shfl_xor_sync(0xffffffffu, pa, o);
        pb += __shfl_xor_sync(0xffffffffu, pb, o);
    }
    if (lane == 0) {
        alpha[b * NPIX + rem] = pa;
        beta [b * NPIX + rem] = pb;
    }
}

// ---------------- GEMM: G[p][i] = sum_j A[p][j] * M[i][j]  (128x128 tile) --------
__global__ void __launch_bounds__(256) gemm_g_kernel(
    const float* __restrict__ A, const float* __restrict__ Mw, float* __restrict__ G)
{
    __shared__ float a_s[16][132];
    __shared__ float m_s[16][132];
    const int row0 = blockIdx.x * 128;
    const int tid = threadIdx.x;
    const int ty = tid >> 4, tx = tid & 15;

    float acc[8][8];
    #pragma unroll
    for (int i = 0; i < 8; i++)
        #pragma unroll
        for (int j = 0; j < 8; j++) acc[i][j] = 0.f;

    const int lrow = tid >> 1;            // 0..127
    const int kq = (tid & 1) * 8;

    for (int kk = 0; kk < 128; kk += 16) {
        float4 v0 = *(const float4*)&A[(size_t)(row0 + lrow) * 128 + kk + kq];
        float4 v1 = *(const float4*)&A[(size_t)(row0 + lrow) * 128 + kk + kq + 4];
        a_s[kq + 0][lrow] = v0.x; a_s[kq + 1][lrow] = v0.y;
        a_s[kq + 2][lrow] = v0.z; a_s[kq + 3][lrow] = v0.w;
        a_s[kq + 4][lrow] = v1.x; a_s[kq + 5][lrow] = v1.y;
        a_s[kq + 6][lrow] = v1.z; a_s[kq + 7][lrow] = v1.w;
        float4 w0 = *(const float4*)&Mw[lrow * 128 + kk + kq];
        float4 w1 = *(const float4*)&Mw[lrow * 128 + kk + kq + 4];
        m_s[kq + 0][lrow] = w0.x; m_s[kq + 1][lrow] = w0.y;
        m_s[kq + 2][lrow] = w0.z; m_s[kq + 3][lrow] = w0.w;
        m_s[kq + 4][lrow] = w1.x; m_s[kq + 5][lrow] = w1.y;
        m_s[kq + 6][lrow] = w1.z; m_s[kq + 7][lrow] = w1.w;
        __syncthreads();
        #pragma unroll
        for (int k = 0; k < 16; k++) {
            float ar[8], mr[8];
            float4 t0 = *(const float4*)&a_s[k][ty * 8];
            float4 t1 = *(const float4*)&a_s[k][ty * 8 + 4];
            ar[0]=t0.x; ar[1]=t0.y; ar[2]=t0.z; ar[3]=t0.w;
            ar[4]=t1.x; ar[5]=t1.y; ar[6]=t1.z; ar[7]=t1.w;
            float4 s0 = *(const float4*)&m_s[k][tx * 8];
            float4 s1 = *(const float4*)&m_s[k][tx * 8 + 4];
            mr[0]=s0.x; mr[1]=s0.y; mr[2]=s0.z; mr[3]=s0.w;
            mr[4]=s1.x; mr[5]=s1.y; mr[6]=s1.z; mr[7]=s1.w;
            #pragma unroll
            for (int i = 0; i < 8; i++)
                #pragma unroll
                for (int j = 0; j < 8; j++)
                    acc[i][j] += ar[i] * mr[j];
        }
        __syncthreads();
    }
    #pragma unroll
    for (int i = 0; i < 8; i++) {
        float* gp = &G[(size_t)(row0 + ty * 8 + i) * 128 + tx * 8];
        *(float4*)&gp[0] = make_float4(acc[i][0], acc[i][1], acc[i][2], acc[i][3]);
        *(float4*)&gp[4] = make_float4(acc[i][4], acc[i][5], acc[i][6], acc[i][7]);
    }
}

// ---------------- 25-tap attention on NHWC a/g --------------------------------
__global__ void __launch_bounds__(256) attn_t_kernel(
    const float* __restrict__ at, const float* __restrict__ gt,
    const float* __restrict__ alpha, const float* __restrict__ beta,
    const float* __restrict__ uvc, const float* __restrict__ flow,
    float* __restrict__ fi)
{
    const int warpId = threadIdx.x >> 5;
    const int lane   = threadIdx.x & 31;
    const int pid = blockIdx.x * 8 + warpId;
    const int b = pid >> 14;
    const int rem = pid & 16383;
    const int y = rem >> 7, x = rem & 127;

    float4 q4 = *(const float4*)&at[(size_t)(b * NPIX + rem) * 128 + lane * 4];

    // own-lane tap (for alpha/flow gathers)
    const int tdy = lane / 5 - 2;
    const int tdx = lane - (lane / 5) * 5 - 2;
    const int tny = y + tdy, tnx = x + tdx;
    const bool lvalid = (lane < 25) && (unsigned)tny < 128u && (unsigned)tnx < 128u;
    const int tpix = lvalid ? tny * 128 + tnx : 0;
    float av  = lvalid ? alpha[b * NPIX + tpix] : 0.f;
    float fwx = lvalid ? flow[(b * 2 + 0) * NPIX + tpix] : 0.f;
    float fwy = lvalid ? flow[(b * 2 + 1) * NPIX + tpix] : 0.f;

    float part[25];
    #pragma unroll
    for (int tt = 0; tt < 25; tt++) {
        const int ny = y + tt / 5 - 2;
        const int nx = x + tt % 5 - 2;
        if ((unsigned)ny < 128u && (unsigned)nx < 128u) {
            float4 g4 = *(const float4*)&gt[(size_t)(b * NPIX + ny * 128 + nx) * 128 + lane * 4];
            part[tt] = q4.x * g4.x + q4.y * g4.y + q4.z * g4.z + q4.w * g4.w;
        } else part[tt] = 0.f;
    }
    #pragma unroll
    for (int o = 16; o > 0; o >>= 1)
        #pragma unroll
        for (int tt = 0; tt < 25; tt++)
            part[tt] += __shfl_xor_sync(0xffffffffu, part[tt], o);

    const float bp = beta[b * NPIX + rem];
    const float cv = uvc[256];
    const float SCALE = 0.08838834764831845f;   // 1/sqrt(128)

    float m = -1e30f;
    #pragma unroll
    for (int tt = 0; tt < 25; tt++) {
        const int ny = y + tt / 5 - 2;
        const int nx = x + tt % 5 - 2;
        const bool vv = (unsigned)ny < 128u && (unsigned)nx < 128u;
        float s = vv ? (part[tt] + __shfl_sync(0xffffffffu, av, tt) + bp + cv) * SCALE : 0.f;
        part[tt] = s;
        m = fmaxf(m, s);
    }
    float sum = 0.f, ox = 0.f, oy = 0.f;
    #pragma unroll
    for (int tt = 0; tt < 25; tt++) {
        float e = expf(part[tt] - m);
        sum += e;
        ox += e * __shfl_sync(0xffffffffu, fwx, tt);
        oy += e * __shfl_sync(0xffffffffu, fwy, tt);
    }
    if (lane == 0) {
        fi[(b * 2 + 0) * NPIX + rem] = ox / sum;
        fi[(b * 2 + 1) * NPIX + rem] = oy / sum;
    }
}

// ---------------- fused fr refiner: fi -> d1 -> d2 -> flow += d3 -----------------
// The reference zero-pads the INTERMEDIATE tensors d1 and d2 at image borders.
// So halo entries of d1_s/d2_s whose global coords fall outside [0,128)^2 must be
// forced to exactly 0, not computed from the conv.
__global__ void __launch_bounds__(256) fr_fused_kernel(
    const float* __restrict__ fi,
    const float* __restrict__ w1, const float* __restrict__ b1,
    const float* __restrict__ w2, const float* __restrict__ b2,
    const float* __restrict__ w3, const float* __restrict__ b3,
    float* __restrict__ flow)
{
    __shared__ float fi_s[2][14][23];
    __shared__ float d1_s[16][12][21];
    __shared__ float d2_s[16][10][19];
    __shared__ float w1_s[288];
    __shared__ float w2_s[2304];
    __shared__ float w3_s[288];

    const int tid = threadIdx.x;
    const int bx = blockIdx.x;          // 0..127
    const int b  = blockIdx.y;
    const int tx0 = (bx & 7) * 16;
    const int ty0 = (bx >> 3) * 8;

    for (int i = tid; i < 288; i += 256) w1_s[i] = w1[i];
    for (int i = tid; i < 2304; i += 256) w2_s[i] = w2[i];
    for (int i = tid; i < 288; i += 256) w3_s[i] = w3[i];

    // fi tile: 2ch x 14 x 22, origin (ty0-3, tx0-3); fi itself is zero-padded
    for (int idx = tid; idx < 2 * 14 * 22; idx += 256) {
        int ci = idx / 308;
        int r  = (idx / 22) % 14;
        int c  = idx % 22;
        int gy = ty0 - 3 + r, gx = tx0 - 3 + c;
        float v = 0.f;
        if ((unsigned)gy < 128u && (unsigned)gx < 128u)
            v = fi[(b * 2 + ci) * NPIX + gy * 128 + gx];
        fi_s[ci][r][c] = v;
    }
    __syncthreads();

    // d1: 16ch x 12 x 20, origin (ty0-2, tx0-2); zero outside image
    for (int o = tid; o < 16 * 12 * 20; o += 256) {
        int co = o / 240;
        int r  = (o / 20) % 12;
        int c  = o % 20;
        int gy = ty0 - 2 + r, gx = tx0 - 2 + c;
        float res = 0.f;
        if ((unsigned)gy < 128u && (unsigned)gx < 128u) {
            float acc = b1[co];
            #pragma unroll
            for (int ci = 0; ci < 2; ci++)
                #pragma unroll
                for (int ky = 0; ky < 3; ky++)
                    #pragma unroll
                    for (int kx = 0; kx < 3; kx++)
                        acc += fi_s[ci][r + ky][c + kx] * w1_s[(co * 2 + ci) * 9 + ky * 3 + kx];
            res = gelu_f(acc);
        }
        d1_s[co][r][c] = res;
    }
    __syncthreads();

    // d2: 16ch x 10 x 18, origin (ty0-1, tx0-1); zero outside image
    for (int o = tid; o < 16 * 10 * 18; o += 256) {
        int co = o / 180;
        int r  = (o / 18) % 10;
        int c  = o % 18;
        int gy = ty0 - 1 + r, gx = tx0 - 1 + c;
        float res = 0.f;
        if ((unsigned)gy < 128u && (unsigned)gx < 128u) {
            float acc = b2[co];
            #pragma unroll
            for (int ci = 0; ci < 16; ci++)
                #pragma unroll
                for (int ky = 0; ky < 3; ky++)
                    #pragma unroll
                    for (int kx = 0; kx < 3; kx++)
                        acc += d1_s[ci][r + ky][c + kx] * w2_s[(co * 16 + ci) * 9 + ky * 3 + kx];
            res = gelu_f(acc);
        }
        d2_s[co][r][c] = res;
    }
    __syncthreads();

    // d3 = conv(d2), flow += d3: 2ch x 8 x 16 (all positions inside image)
    for (int o = tid; o < 2 * 8 * 16; o += 256) {
        int co = o / 128;
        int r  = (o / 16) % 8;
        int c  = o % 16;
        float acc = b3[co];
        #pragma unroll
        for (int ci = 0; ci < 16; ci++)
            #pragma unroll
            for (int ky = 0; ky < 3; ky++)
                #pragma unroll
                for (int kx = 0; kx < 3; kx++)
                    acc += d2_s[ci][r + ky][c + kx] * w3_s[(co * 16 + ci) * 9 + ky * 3 + kx];
        flow[(b * 2 + co) * NPIX + (ty0 + r) * 128 + tx0 + c] += acc;
    }
}

// ---------------- warp feat1 -> hcat channels 128..255 (conf path) ---------------
__global__ void __launch_bounds__(256) warp_feat_kernel(
    const float* __restrict__ feat1, const float* __restrict__ flow,
    float* __restrict__ hcat)
{
    const int warpId = threadIdx.x >> 5;
    const int lane   = threadIdx.x & 31;
    const int pid = blockIdx.x * 8 + warpId;
    const int b = pid >> 14;
    const int rem = pid & 16383;
    const int y = rem >> 7, x = rem & 127;

    float fx = flow[(b * 2 + 0) * NPIX + rem];
    float fy = flow[(b * 2 + 1) * NPIX + rem];
    Bilin bl = bilin_setup(fx, fy, x, y);

    const int cin  = (b * 128 + lane * 4) * NPIX;
    const int cout = (b * 264 + 128 + lane * 4) * NPIX;
    #pragma unroll
    for (int j = 0; j < 4; j++) {
        const float* f1 = feat1 + cin + j * NPIX;
        float v = f1[bl.i00] * bl.w00 + f1[bl.i01] * bl.w01
                + f1[bl.i10] * bl.w10 + f1[bl.i11] * bl.w11;
        hcat[cout + j * NPIX + rem] = v;
    }
}

// ---------------- small direct conv (conf final) ----------------
template<int CIN, int COUT, int ACT, bool ADD>
__global__ void __launch_bounds__(256) conv_small_kernel(
    const float* __restrict__ in, const float* __restrict__ w,
    const float* __restrict__ bias, float* __restrict__ out)
{
    const int idx = blockIdx.x * 256 + threadIdx.x;
    if (idx >= BATCH * COUT * NPIX) return;
    const int rem = idx & 16383;
    const int y = rem >> 7, x = rem & 127;
    const int co = (idx >> 14) % COUT;
    const int b  = idx / (NPIX * COUT);

    float acc = bias[co];
    for (int ci = 0; ci < CIN; ci++) {
        const float* ip = in + (b * CIN + ci) * NPIX;
        const float* wp = w + (co * CIN + ci) * 9;
        #pragma unroll
        for (int ky = 0; ky < 3; ky++) {
            int gy = y + ky - 1;
            if ((unsigned)gy >= 128u) continue;
            #pragma unroll
            for (int kx = 0; kx < 3; kx++) {
                int gx = x + kx - 1;
                if ((unsigned)gx >= 128u) continue;
                acc += ip[gy * 128 + gx] * wp[ky * 3 + kx];
            }
        }
    }
    if (ACT == 1) acc = gelu_f(acc);
    if (ACT == 2) acc = 1.f / (1.f + expf(-acc));
    if (ADD) out[idx] += acc;
    else     out[idx] = acc;
}

// ---------------- misc ----------------
__global__ void copy_kernel(const float* __restrict__ src, float* __restrict__ dst, int n) {
    int i = blockIdx.x * 256 + threadIdx.x;
    if (i < n) dst[i] = src[i];
}

__global__ void hcat_feat0_kernel(const float* __restrict__ feat0, float* __restrict__ hcat) {
    int idx = blockIdx.x * 256 + threadIdx.x;
    if (idx >= BATCH * 128 * NPIX) return;
    int p = idx & 16383;
    int c = (idx >> 14) & 127;
    int b = idx >> 21;
    hcat[(b * 264 + c) * NPIX + p] = feat0[idx];
}

__global__ void hcat_tail_kernel(const float* __restrict__ flow, float* __restrict__ hcat) {
    int idx = blockIdx.x * 256 + threadIdx.x;
    if (idx >= BATCH * 8 * NPIX) return;
    int p = idx & 16383;
    int c2 = (idx >> 14) & 7;
    int b = idx / (8 * NPIX);
    float v = (c2 < 2) ? flow[(b * 2 + c2) * NPIX + p] : 0.f;
    hcat[(b * 264 + 256 + c2) * NPIX + p] = v;
}

// ---------------- host launch ----------------
extern "C" void kernel_launch(void* const* d_in, const int* in_sizes, int n_in,
                              void* d_out, int out_size)
{
    const float* feat0     = (const float*)d_in[0];
    const float* feat1     = (const float*)d_in[1];
    const float* flow_init = (const float*)d_in[2];
    const float* lc_w1 = (const float*)d_in[3];
    const float* lc_b1 = (const float*)d_in[4];
    const float* lc_w2 = (const float*)d_in[5];
    const float* lc_b2 = (const float*)d_in[6];
    const float* qw = (const float*)d_in[7];
    const float* qb = (const float*)d_in[8];
    const float* kw = (const float*)d_in[9];
    const float* kb = (const float*)d_in[10];
    const float* fr_w1 = (const float*)d_in[11];
    const float* fr_b1 = (const float*)d_in[12];
    const float* fr_w2 = (const float*)d_in[13];
    const float* fr_b2 = (const float*)d_in[14];
    const float* fr_w3 = (const float*)d_in[15];
    const float* fr_b3 = (const float*)d_in[16];
    const float* cf_w1 = (const float*)d_in[17];
    const float* cf_b1 = (const float*)d_in[18];
    const float* cf_w2 = (const float*)d_in[19];
    const float* cf_b2 = (const float*)d_in[20];
    const float* cf_w3 = (const float*)d_in[21];
    const float* cf_b3 = (const float*)d_in[22];
    float* out = (float*)d_out;

    float *p_lf0, *p_lf1, *p_lf0t, *p_lf1t, *p_tmp, *p_at, *p_gt, *p_alpha, *p_beta;
    float *p_flow, *p_fi, *p_hcat, *p_h2, *p_Mw, *p_uvc;
    cudaGetSymbolAddress((void**)&p_lf0,  g_lf0);
    cudaGetSymbolAddress((void**)&p_lf1,  g_lf1);
    cudaGetSymbolAddress((void**)&p_lf0t, g_lf0t);
    cudaGetSymbolAddress((void**)&p_lf1t, g_lf1t);
    cudaGetSymbolAddress((void**)&p_tmp,  g_tmp);
    cudaGetSymbolAddress((void**)&p_at,   g_at);
    cudaGetSymbolAddress((void**)&p_gt,   g_gt);
    cudaGetSymbolAddress((void**)&p_alpha,g_alpha);
    cudaGetSymbolAddress((void**)&p_beta, g_beta);
    cudaGetSymbolAddress((void**)&p_flow, g_flow);
    cudaGetSymbolAddress((void**)&p_fi,   g_fi);
    cudaGetSymbolAddress((void**)&p_hcat, g_hcat);
    cudaGetSymbolAddress((void**)&p_h2,   g_h2);
    cudaGetSymbolAddress((void**)&p_Mw,   g_Mw);
    cudaGetSymbolAddress((void**)&p_uvc,  g_uvc);

    dim3 cgrid(32, 8, BATCH);   // 4x8 spatial tiles (32x16 px), 8 co-groups

    // local_conv on both features
    conv3x3_kernel<1><<<cgrid, 256>>>(feat0, lc_w1, lc_b1, p_tmp, 128, 128, 128);
    conv3x3_kernel<0><<<cgrid, 256>>>(p_tmp, lc_w2, lc_b2, p_lf0, 128, 128, 128);
    conv3x3_kernel<1><<<cgrid, 256>>>(feat1, lc_w1, lc_b1, p_tmp, 128, 128, 128);
    conv3x3_kernel<0><<<cgrid, 256>>>(p_tmp, lc_w2, lc_b2, p_lf1, 128, 128, 128);

    // NHWC copies of lf0/lf1 (loop-invariant)
    transpose_kernel<<<dim3(512, 4, BATCH), 256>>>(p_lf0, p_lf0t);
    transpose_kernel<<<dim3(512, 4, BATCH), 256>>>(p_lf1, p_lf1t);

    // attention weight precomputation (once)
    prep_M_kernel<<<64, 256>>>(qw, kw, p_Mw);
    prep_uvc_kernel<<<1, 128>>>(qw, qb, kw, kb, p_uvc);

    copy_kernel<<<(BATCH * 2 * NPIX + 255) / 256, 256>>>(flow_init, p_flow, BATCH * 2 * NPIX);

    for (int it = 0; it < 10; it++) {
        warp_diff_t_kernel<<<4096, 256>>>(p_lf0t, p_lf1t, p_flow, p_uvc, p_at, p_alpha, p_beta);
        gemm_g_kernel<<<256, 256>>>(p_at, p_Mw, p_gt);
        attn_t_kernel<<<4096, 256>>>(p_at, p_gt, p_alpha, p_beta, p_uvc, p_flow, p_fi);
        fr_fused_kernel<<<dim3(128, BATCH), 256>>>(p_fi, fr_w1, fr_b1, fr_w2, fr_b2, fr_w3, fr_b3, p_flow);
    }

    // confidence head
    warp_feat_kernel<<<4096, 256>>>(feat1, p_flow, p_hcat);
    hcat_feat0_kernel<<<(BATCH * 128 * NPIX + 255) / 256, 256>>>(feat0, p_hcat);
    hcat_tail_kernel<<<(BATCH * 8 * NPIX + 255) / 256, 256>>>(p_flow, p_hcat);
    conv3x3_kernel<1><<<cgrid, 256>>>(p_hcat, cf_w1, cf_b1, p_tmp, 258, 264, 128);
    conv3x3_kernel<1><<<dim3(32, 4, BATCH), 256>>>(p_tmp, cf_w2, cf_b2, p_h2, 128, 128, 64);
    conv_small_kernel<64, 1, 2, false><<<(BATCH * NPIX + 255) / 256, 256>>>(p_h2, cf_w3, cf_b3, out + BATCH * 2 * NPIX);

    copy_kernel<<<(BATCH * 2 * NPIX + 255) / 256, 256>>>(p_flow, out, BATCH * 2 * NPIX);
}

// round 11
// speedup vs baseline: 1.0820x; 1.0820x over previous
#include <cuda_runtime.h>
#include <math.h>

#define NPIX 16384          // 128*128
#define BATCH 2

// ---------------- scratch (static device memory; no allocations) ----------------
__device__ float g_lf0 [BATCH*128*NPIX];   // NCHW
__device__ float g_lf1 [BATCH*128*NPIX];   // NCHW
__device__ float g_lf0t[BATCH*NPIX*128];   // NHWC
__device__ float g_lf1t[BATCH*NPIX*128];   // NHWC
__device__ float g_tmp [BATCH*128*NPIX];
__device__ float g_at  [BATCH*NPIX*128];   // a, NHWC (also reused as tmp1 pre-loop)
__device__ float g_gt  [BATCH*NPIX*128];   // g = M·a, NHWC
__device__ float g_alpha[BATCH*NPIX];
__device__ float g_beta [BATCH*NPIX];
__device__ float g_flow[BATCH*2*NPIX];
__device__ float g_fi  [BATCH*2*NPIX];
__device__ float g_hcat[BATCH*264*NPIX];   // 258 real channels zero-padded to 264
__device__ float g_h2  [BATCH*64*NPIX];
__device__ float g_Mw  [128*128];          // M[i][j] = sum_d qw[d,i]*kw[d,j]
__device__ float g_uvc [260];              // u[0..127], v[128..255], c at [256]

__device__ __forceinline__ float gelu_f(float x) {
    return 0.5f * x * (1.0f + erff(x * 0.7071067811865476f));
}

// ---------------- generic 3x3 conv: tile 16x16 px, 16 co per block (R7) ----------
template<int ACT>   // 0=none, 1=gelu
__device__ __forceinline__ void conv3x3_body(
    const float* __restrict__ in, const float* __restrict__ w,
    const float* __restrict__ bias, float* __restrict__ out,
    int Cin, int CinPad, int Cout, int tile, int cog, int b,
    float in_s[8][18][20], float w_s[8][9][16])
{
    const int tid = threadIdx.x;
    const int tx0 = (tile & 7) * 16;
    const int ty0 = (tile >> 3) * 16;
    const int cg  = tid >> 6;
    const int p   = tid & 63;
    const int qy  = (p >> 3) * 2;
    const int qx  = (p & 7) * 2;

    float acc[4][2][2];
    #pragma unroll
    for (int i = 0; i < 4; i++)
        #pragma unroll
        for (int dy = 0; dy < 2; dy++)
            #pragma unroll
            for (int dx = 0; dx < 2; dx++) acc[i][dy][dx] = 0.f;

    const int nchunk = CinPad >> 3;
    for (int ch = 0; ch < nchunk; ch++) {
        const int ci0 = ch * 8;
        for (int idx = tid; idx < 8 * 18 * 18; idx += 256) {
            int ci = idx / 324;
            int rem = idx - ci * 324;
            int r = rem / 18;
            int c = rem - r * 18;
            int gy = ty0 - 1 + r, gx = tx0 - 1 + c;
            float v = 0.f;
            if ((unsigned)gy < 128u && (unsigned)gx < 128u)
                v = in[((b * CinPad + ci0 + ci) << 14) + (gy << 7) + gx];
            in_s[ci][r][c] = v;
        }
        for (int idx = tid; idx < 8 * 9 * 16; idx += 256) {
            int col = idx & 15;
            int rem = idx >> 4;
            int k = rem % 9;
            int ci = rem / 9;
            int cig = ci0 + ci;
            float v = (cig < Cin) ? w[((cog + col) * Cin + cig) * 9 + k] : 0.f;
            w_s[ci][k][col] = v;
        }
        __syncthreads();
        #pragma unroll
        for (int ci = 0; ci < 8; ci++) {
            float v[4][4];
            #pragma unroll
            for (int r = 0; r < 4; r++) {
                float2 a0 = *(const float2*)&in_s[ci][qy + r][qx];
                float2 a1 = *(const float2*)&in_s[ci][qy + r][qx + 2];
                v[r][0] = a0.x; v[r][1] = a0.y; v[r][2] = a1.x; v[r][3] = a1.y;
            }
            #pragma unroll
            for (int k = 0; k < 9; k++) {
                const int ky = k / 3, kx = k % 3;
                float4 wv = *(const float4*)&w_s[ci][k][cg * 4];
                #pragma unroll
                for (int dy = 0; dy < 2; dy++)
                    #pragma unroll
                    for (int dx = 0; dx < 2; dx++) {
                        float iv = v[ky + dy][kx + dx];
                        acc[0][dy][dx] += wv.x * iv;
                        acc[1][dy][dx] += wv.y * iv;
                        acc[2][dy][dx] += wv.z * iv;
                        acc[3][dy][dx] += wv.w * iv;
                    }
            }
        }
        __syncthreads();
    }
    #pragma unroll
    for (int i = 0; i < 4; i++) {
        int co = cog + cg * 4 + i;
        float bv = bias[co];
        #pragma unroll
        for (int dy = 0; dy < 2; dy++)
            #pragma unroll
            for (int dx = 0; dx < 2; dx++) {
                float r = acc[i][dy][dx] + bv;
                if (ACT == 1) r = gelu_f(r);
                out[((b * Cout + co) << 14) + ((ty0 + qy + dy) << 7) + (tx0 + qx + dx)] = r;
            }
    }
}

template<int ACT>
__global__ void __launch_bounds__(256) conv3x3_kernel(
    const float* __restrict__ in, const float* __restrict__ w,
    const float* __restrict__ bias, float* __restrict__ out,
    int Cin, int CinPad, int Cout)
{
    __shared__ float in_s[8][18][20];
    __shared__ float w_s[8][9][16];
    conv3x3_body<ACT>(in, w, bias, out, Cin, CinPad, Cout,
                      blockIdx.x, blockIdx.y * 16, blockIdx.z, in_s, w_s);
}

// Dual-input variant: z = sel*BATCH + b runs the same conv on (in0,out0) or
// (in1,out1). Packs the independent feat0/feat1 chains into one launch
// (2048 blocks = 2.77 waves instead of 2x 1024-block launches at 1.38 waves
// each) to cut wave-tail idle. Identical per-output math.
template<int ACT>
__global__ void __launch_bounds__(256) conv3x3_dual_kernel(
    const float* __restrict__ in0, const float* __restrict__ in1,
    const float* __restrict__ w, const float* __restrict__ bias,
    float* __restrict__ out0, float* __restrict__ out1)
{
    __shared__ float in_s[8][18][20];
    __shared__ float w_s[8][9][16];
    const int z = blockIdx.z;
    const int b = z & (BATCH - 1);
    const int sel = z >> 1;
    conv3x3_body<ACT>(sel ? in1 : in0, w, bias, sel ? out1 : out0,
                      128, 128, 128, blockIdx.x, blockIdx.y * 16, b, in_s, w_s);
}

// ---------------- NCHW [128][NPIX] -> NHWC [NPIX][128] transpose ----------------
__global__ void __launch_bounds__(256) transpose_kernel(
    const float* __restrict__ in, float* __restrict__ out)
{
    __shared__ float t[32][33];
    const int b  = blockIdx.z;
    const int p0 = blockIdx.x * 32;
    const int c0 = blockIdx.y * 32;
    const int x  = threadIdx.x & 31;
    const int yy = threadIdx.x >> 5;
    #pragma unroll
    for (int i = 0; i < 4; i++)
        t[yy + i * 8][x] = in[(b * 128 + c0 + yy + i * 8) * NPIX + p0 + x];
    __syncthreads();
    #pragma unroll
    for (int i = 0; i < 4; i++)
        out[(b * NPIX + p0 + yy + i * 8) * 128 + c0 + x] = t[x][yy + i * 8];
}

// ---------------- prep: M[i][j] = sum_d qw[d*128+i]*kw[d*128+j] ----------------
__global__ void __launch_bounds__(256) prep_M_kernel(
    const float* __restrict__ qw, const float* __restrict__ kw, float* __restrict__ Mw)
{
    int t = blockIdx.x * 256 + threadIdx.x;     // 64 blocks -> 16384
    int i = t >> 7, j = t & 127;
    float s = 0.f;
    for (int d = 0; d < 128; d++)
        s += qw[d * 128 + i] * kw[d * 128 + j];
    Mw[i * 128 + j] = s;
}

__global__ void prep_uvc_kernel(
    const float* __restrict__ qw, const float* __restrict__ qb,
    const float* __restrict__ kw, const float* __restrict__ kb,
    float* __restrict__ uvc)
{
    int j = threadIdx.x;   // 128 threads
    float u = 0.f, v = 0.f;
    for (int d = 0; d < 128; d++) {
        u += qb[d] * kw[d * 128 + j];
        v += qw[d * 128 + j] * kb[d];
    }
    uvc[j] = u;
    uvc[128 + j] = v;
    if (j == 0) {
        float c = 0.f;
        for (int d = 0; d < 128; d++) c += qb[d] * kb[d];
        uvc[256] = c;
    }
}

// ---------------- bilinear setup ----------------
struct Bilin { int i00, i01, i10, i11; float w00, w01, w10, w11; };
__device__ __forceinline__ Bilin bilin_setup(float fx, float fy, int x, int y) {
    float xf = fminf(fmaxf((float)x + fx, 0.f), 127.f);
    float yf = fminf(fmaxf((float)y + fy, 0.f), 127.f);
    float x0f = floorf(xf), y0f = floorf(yf);
    int x0 = (int)x0f, y0 = (int)y0f;
    int x1 = min(x0 + 1, 127), y1 = min(y0 + 1, 127);
    float wx = xf - x0f, wy = yf - y0f;
    Bilin r;
    r.i00 = y0 * 128 + x0; r.i01 = y0 * 128 + x1;
    r.i10 = y1 * 128 + x0; r.i11 = y1 * 128 + x1;
    r.w00 = (1.f - wx) * (1.f - wy); r.w01 = wx * (1.f - wy);
    r.w10 = (1.f - wx) * wy;         r.w11 = wx * wy;
    return r;
}

// ---------------- warp+diff+norm, NHWC, also emits alpha/beta -------------------
__global__ void __launch_bounds__(256) warp_diff_t_kernel(
    const float* __restrict__ lf0t, const float* __restrict__ lf1t,
    const float* __restrict__ flow, const float* __restrict__ uvc,
    float* __restrict__ at, float* __restrict__ alpha, float* __restrict__ beta)
{
    const int warpId = threadIdx.x >> 5;
    const int lane   = threadIdx.x & 31;
    const int pid = blockIdx.x * 8 + warpId;
    const int b = pid >> 14;
    const int rem = pid & 16383;
    const int y = rem >> 7, x = rem & 127;

    float fx = flow[(b * 2 + 0) * NPIX + rem];
    float fy = flow[(b * 2 + 1) * NPIX + rem];
    Bilin bl = bilin_setup(fx, fy, x, y);

    const float* l1 = lf1t + (size_t)(b * NPIX) * 128 + lane * 4;
    float4 f00 = *(const float4*)&l1[bl.i00 * 128];
    float4 f01 = *(const float4*)&l1[bl.i01 * 128];
    float4 f10 = *(const float4*)&l1[bl.i10 * 128];
    float4 f11 = *(const float4*)&l1[bl.i11 * 128];
    float4 x0 = *(const float4*)&lf0t[(size_t)(b * NPIX + rem) * 128 + lane * 4];

    float4 d;
    d.x = x0.x - (f00.x * bl.w00 + f01.x * bl.w01 + f10.x * bl.w10 + f11.x * bl.w11);
    d.y = x0.y - (f00.y * bl.w00 + f01.y * bl.w01 + f10.y * bl.w10 + f11.y * bl.w11);
    d.z = x0.z - (f00.z * bl.w00 + f01.z * bl.w01 + f10.z * bl.w10 + f11.z * bl.w11);
    d.w = x0.w - (f00.w * bl.w00 + f01.w * bl.w01 + f10.w * bl.w10 + f11.w * bl.w11);

    float ss = d.x * d.x + d.y * d.y + d.z * d.z + d.w * d.w;
    #pragma unroll
    for (int o = 16; o > 0; o >>= 1) ss += __shfl_xor_sync(0xffffffffu, ss, o);
    float inv = 1.f / fmaxf(sqrtf(ss), 1e-12f);

    float4 a4;
    a4.x = 1.f - d.x * inv; a4.y = 1.f - d.y * inv;
    a4.z = 1.f - d.z * inv; a4.w = 1.f - d.w * inv;
    *(float4*)&at[(size_t)(b * NPIX + rem) * 128 + lane * 4] = a4;

    float4 u4 = *(const float4*)&uvc[lane * 4];
    float4 v4 = *(const float4*)&uvc[128 + lane * 4];
    float pa = u4.x * a4.x + u4.y * a4.y + u4.z * a4.z + u4.w * a4.w;
    float pb = v4.x * a4.x + v4.y * a4.y + v4.z * a4.z + v4.w * a4.w;
    #pragma unroll
    for (int o = 16; o > 0; o >>= 1) {
        pa += __shfl_xor_sync(0xffffffffu, pa, o);
        pb += __shfl_xor_sync(0xffffffffu, pb, o);
    }
    if (lane == 0) {
        alpha[b * NPIX + rem] = pa;
        beta [b * NPIX + rem] = pb;
    }
}

// ---------------- GEMM: G[p][i] = sum_j A[p][j] * M[i][j]  (128x128 tile) --------
__global__ void __launch_bounds__(256) gemm_g_kernel(
    const float* __restrict__ A, const float* __restrict__ Mw, float* __restrict__ G)
{
    __shared__ float a_s[16][132];
    __shared__ float m_s[16][132];
    const int row0 = blockIdx.x * 128;
    const int tid = threadIdx.x;
    const int ty = tid >> 4, tx = tid & 15;

    float acc[8][8];
    #pragma unroll
    for (int i = 0; i < 8; i++)
        #pragma unroll
        for (int j = 0; j < 8; j++) acc[i][j] = 0.f;

    const int lrow = tid >> 1;            // 0..127
    const int kq = (tid & 1) * 8;

    for (int kk = 0; kk < 128; kk += 16) {
        float4 v0 = *(const float4*)&A[(size_t)(row0 + lrow) * 128 + kk + kq];
        float4 v1 = *(const float4*)&A[(size_t)(row0 + lrow) * 128 + kk + kq + 4];
        a_s[kq + 0][lrow] = v0.x; a_s[kq + 1][lrow] = v0.y;
        a_s[kq + 2][lrow] = v0.z; a_s[kq + 3][lrow] = v0.w;
        a_s[kq + 4][lrow] = v1.x; a_s[kq + 5][lrow] = v1.y;
        a_s[kq + 6][lrow] = v1.z; a_s[kq + 7][lrow] = v1.w;
        float4 w0 = *(const float4*)&Mw[lrow * 128 + kk + kq];
        float4 w1 = *(const float4*)&Mw[lrow * 128 + kk + kq + 4];
        m_s[kq + 0][lrow] = w0.x; m_s[kq + 1][lrow] = w0.y;
        m_s[kq + 2][lrow] = w0.z; m_s[kq + 3][lrow] = w0.w;
        m_s[kq + 4][lrow] = w1.x; m_s[kq + 5][lrow] = w1.y;
        m_s[kq + 6][lrow] = w1.z; m_s[kq + 7][lrow] = w1.w;
        __syncthreads();
        #pragma unroll
        for (int k = 0; k < 16; k++) {
            float ar[8], mr[8];
            float4 t0 = *(const float4*)&a_s[k][ty * 8];
            float4 t1 = *(const float4*)&a_s[k][ty * 8 + 4];
            ar[0]=t0.x; ar[1]=t0.y; ar[2]=t0.z; ar[3]=t0.w;
            ar[4]=t1.x; ar[5]=t1.y; ar[6]=t1.z; ar[7]=t1.w;
            float4 s0 = *(const float4*)&m_s[k][tx * 8];
            float4 s1 = *(const float4*)&m_s[k][tx * 8 + 4];
            mr[0]=s0.x; mr[1]=s0.y; mr[2]=s0.z; mr[3]=s0.w;
            mr[4]=s1.x; mr[5]=s1.y; mr[6]=s1.z; mr[7]=s1.w;
            #pragma unroll
            for (int i = 0; i < 8; i++)
                #pragma unroll
                for (int j = 0; j < 8; j++)
                    acc[i][j] += ar[i] * mr[j];
        }
        __syncthreads();
    }
    #pragma unroll
    for (int i = 0; i < 8; i++) {
        float* gp = &G[(size_t)(row0 + ty * 8 + i) * 128 + tx * 8];
        *(float4*)&gp[0] = make_float4(acc[i][0], acc[i][1], acc[i][2], acc[i][3]);
        *(float4*)&gp[4] = make_float4(acc[i][4], acc[i][5], acc[i][6], acc[i][7]);
    }
}

// ---------------- 25-tap attention on NHWC a/g --------------------------------
__global__ void __launch_bounds__(256) attn_t_kernel(
    const float* __restrict__ at, const float* __restrict__ gt,
    const float* __restrict__ alpha, const float* __restrict__ beta,
    const float* __restrict__ uvc, const float* __restrict__ flow,
    float* __restrict__ fi)
{
    const int warpId = threadIdx.x >> 5;
    const int lane   = threadIdx.x & 31;
    const int pid = blockIdx.x * 8 + warpId;
    const int b = pid >> 14;
    const int rem = pid & 16383;
    const int y = rem >> 7, x = rem & 127;

    float4 q4 = *(const float4*)&at[(size_t)(b * NPIX + rem) * 128 + lane * 4];

    // own-lane tap (for alpha/flow gathers)
    const int tdy = lane / 5 - 2;
    const int tdx = lane - (lane / 5) * 5 - 2;
    const int tny = y + tdy, tnx = x + tdx;
    const bool lvalid = (lane < 25) && (unsigned)tny < 128u && (unsigned)tnx < 128u;
    const int tpix = lvalid ? tny * 128 + tnx : 0;
    float av  = lvalid ? alpha[b * NPIX + tpix] : 0.f;
    float fwx = lvalid ? flow[(b * 2 + 0) * NPIX + tpix] : 0.f;
    float fwy = lvalid ? flow[(b * 2 + 1) * NPIX + tpix] : 0.f;

    float part[25];
    #pragma unroll
    for (int tt = 0; tt < 25; tt++) {
        const int ny = y + tt / 5 - 2;
        const int nx = x + tt % 5 - 2;
        if ((unsigned)ny < 128u && (unsigned)nx < 128u) {
            float4 g4 = *(const float4*)&gt[(size_t)(b * NPIX + ny * 128 + nx) * 128 + lane * 4];
            part[tt] = q4.x * g4.x + q4.y * g4.y + q4.z * g4.z + q4.w * g4.w;
        } else part[tt] = 0.f;
    }
    #pragma unroll
    for (int o = 16; o > 0; o >>= 1)
        #pragma unroll
        for (int tt = 0; tt < 25; tt++)
            part[tt] += __shfl_xor_sync(0xffffffffu, part[tt], o);

    const float bp = beta[b * NPIX + rem];
    const float cv = uvc[256];
    const float SCALE = 0.08838834764831845f;   // 1/sqrt(128)

    float m = -1e30f;
    #pragma unroll
    for (int tt = 0; tt < 25; tt++) {
        const int ny = y + tt / 5 - 2;
        const int nx = x + tt % 5 - 2;
        const bool vv = (unsigned)ny < 128u && (unsigned)nx < 128u;
        float s = vv ? (part[tt] + __shfl_sync(0xffffffffu, av, tt) + bp + cv) * SCALE : 0.f;
        part[tt] = s;
        m = fmaxf(m, s);
    }
    float sum = 0.f, ox = 0.f, oy = 0.f;
    #pragma unroll
    for (int tt = 0; tt < 25; tt++) {
        float e = expf(part[tt] - m);
        sum += e;
        ox += e * __shfl_sync(0xffffffffu, fwx, tt);
        oy += e * __shfl_sync(0xffffffffu, fwy, tt);
    }
    if (lane == 0) {
        fi[(b * 2 + 0) * NPIX + rem] = ox / sum;
        fi[(b * 2 + 1) * NPIX + rem] = oy / sum;
    }
}

// ---------------- fused fr refiner: fi -> d1 -> d2 -> flow += d3 -----------------
// The reference zero-pads the INTERMEDIATE tensors d1 and d2 at image borders.
// So halo entries of d1_s/d2_s whose global coords fall outside [0,128)^2 must be
// forced to exactly 0, not computed from the conv.
__global__ void __launch_bounds__(256) fr_fused_kernel(
    const float* __restrict__ fi,
    const float* __restrict__ w1, const float* __restrict__ b1,
    const float* __restrict__ w2, const float* __restrict__ b2,
    const float* __restrict__ w3, const float* __restrict__ b3,
    float* __restrict__ flow)
{
    __shared__ float fi_s[2][14][23];
    __shared__ float d1_s[16][12][21];
    __shared__ float d2_s[16][10][19];
    __shared__ float w1_s[288];
    __shared__ float w2_s[2304];
    __shared__ float w3_s[288];

    const int tid = threadIdx.x;
    const int bx = blockIdx.x;          // 0..127
    const int b  = blockIdx.y;
    const int tx0 = (bx & 7) * 16;
    const int ty0 = (bx >> 3) * 8;

    for (int i = tid; i < 288; i += 256) w1_s[i] = w1[i];
    for (int i = tid; i < 2304; i += 256) w2_s[i] = w2[i];
    for (int i = tid; i < 288; i += 256) w3_s[i] = w3[i];

    // fi tile: 2ch x 14 x 22, origin (ty0-3, tx0-3); fi itself is zero-padded
    for (int idx = tid; idx < 2 * 14 * 22; idx += 256) {
        int ci = idx / 308;
        int r  = (idx / 22) % 14;
        int c  = idx % 22;
        int gy = ty0 - 3 + r, gx = tx0 - 3 + c;
        float v = 0.f;
        if ((unsigned)gy < 128u && (unsigned)gx < 128u)
            v = fi[(b * 2 + ci) * NPIX + gy * 128 + gx];
        fi_s[ci][r][c] = v;
    }
    __syncthreads();

    // d1: 16ch x 12 x 20, origin (ty0-2, tx0-2); zero outside image
    for (int o = tid; o < 16 * 12 * 20; o += 256) {
        int co = o / 240;
        int r  = (o / 20) % 12;
        int c  = o % 20;
        int gy = ty0 - 2 + r, gx = tx0 - 2 + c;
        float res = 0.f;
        if ((unsigned)gy < 128u && (unsigned)gx < 128u) {
            float acc = b1[co];
            #pragma unroll
            for (int ci = 0; ci < 2; ci++)
                #pragma unroll
                for (int ky = 0; ky < 3; ky++)
                    #pragma unroll
                    for (int kx = 0; kx < 3; kx++)
                        acc += fi_s[ci][r + ky][c + kx] * w1_s[(co * 2 + ci) * 9 + ky * 3 + kx];
            res = gelu_f(acc);
        }
        d1_s[co][r][c] = res;
    }
    __syncthreads();

    // d2: 16ch x 10 x 18, origin (ty0-1, tx0-1); zero outside image
    for (int o = tid; o < 16 * 10 * 18; o += 256) {
        int co = o / 180;
        int r  = (o / 18) % 10;
        int c  = o % 18;
        int gy = ty0 - 1 + r, gx = tx0 - 1 + c;
        float res = 0.f;
        if ((unsigned)gy < 128u && (unsigned)gx < 128u) {
            float acc = b2[co];
            #pragma unroll
            for (int ci = 0; ci < 16; ci++)
                #pragma unroll
                for (int ky = 0; ky < 3; ky++)
                    #pragma unroll
                    for (int kx = 0; kx < 3; kx++)
                        acc += d1_s[ci][r + ky][c + kx] * w2_s[(co * 16 + ci) * 9 + ky * 3 + kx];
            res = gelu_f(acc);
        }
        d2_s[co][r][c] = res;
    }
    __syncthreads();

    // d3 = conv(d2), flow += d3: 2ch x 8 x 16 (all positions inside image)
    for (int o = tid; o < 2 * 8 * 16; o += 256) {
        int co = o / 128;
        int r  = (o / 16) % 8;
        int c  = o % 16;
        float acc = b3[co];
        #pragma unroll
        for (int ci = 0; ci < 16; ci++)
            #pragma unroll
            for (int ky = 0; ky < 3; ky++)
                #pragma unroll
                for (int kx = 0; kx < 3; kx++)
                    acc += d2_s[ci][r + ky][c + kx] * w3_s[(co * 16 + ci) * 9 + ky * 3 + kx];
        flow[(b * 2 + co) * NPIX + (ty0 + r) * 128 + tx0 + c] += acc;
    }
}

// ---------------- warp feat1 -> hcat channels 128..255 (conf path) ---------------
__global__ void __launch_bounds__(256) warp_feat_kernel(
    const float* __restrict__ feat1, const float* __restrict__ flow,
    float* __restrict__ hcat)
{
    const int warpId = threadIdx.x >> 5;
    const int lane   = threadIdx.x & 31;
    const int pid = blockIdx.x * 8 + warpId;
    const int b = pid >> 14;
    const int rem = pid & 16383;
    const int y = rem >> 7, x = rem & 127;

    float fx = flow[(b * 2 + 0) * NPIX + rem];
    float fy = flow[(b * 2 + 1) * NPIX + rem];
    Bilin bl = bilin_setup(fx, fy, x, y);

    const int cin  = (b * 128 + lane * 4) * NPIX;
    const int cout = (b * 264 + 128 + lane * 4) * NPIX;
    #pragma unroll
    for (int j = 0; j < 4; j++) {
        const float* f1 = feat1 + cin + j * NPIX;
        float v = f1[bl.i00] * bl.w00 + f1[bl.i01] * bl.w01
                + f1[bl.i10] * bl.w10 + f1[bl.i11] * bl.w11;
        hcat[cout + j * NPIX + rem] = v;
    }
}

// ---------------- small direct conv (conf final) ----------------
template<int CIN, int COUT, int ACT, bool ADD>
__global__ void __launch_bounds__(256) conv_small_kernel(
    const float* __restrict__ in, const float* __restrict__ w,
    const float* __restrict__ bias, float* __restrict__ out)
{
    const int idx = blockIdx.x * 256 + threadIdx.x;
    if (idx >= BATCH * COUT * NPIX) return;
    const int rem = idx & 16383;
    const int y = rem >> 7, x = rem & 127;
    const int co = (idx >> 14) % COUT;
    const int b  = idx / (NPIX * COUT);

    float acc = bias[co];
    for (int ci = 0; ci < CIN; ci++) {
        const float* ip = in + (b * CIN + ci) * NPIX;
        const float* wp = w + (co * CIN + ci) * 9;
        #pragma unroll
        for (int ky = 0; ky < 3; ky++) {
            int gy = y + ky - 1;
            if ((unsigned)gy >= 128u) continue;
            #pragma unroll
            for (int kx = 0; kx < 3; kx++) {
                int gx = x + kx - 1;
                if ((unsigned)gx >= 128u) continue;
                acc += ip[gy * 128 + gx] * wp[ky * 3 + kx];
            }
        }
    }
    if (ACT == 1) acc = gelu_f(acc);
    if (ACT == 2) acc = 1.f / (1.f + expf(-acc));
    if (ADD) out[idx] += acc;
    else     out[idx] = acc;
}

// ---------------- misc ----------------
__global__ void copy_kernel(const float* __restrict__ src, float* __restrict__ dst, int n) {
    int i = blockIdx.x * 256 + threadIdx.x;
    if (i < n) dst[i] = src[i];
}

__global__ void hcat_feat0_kernel(const float* __restrict__ feat0, float* __restrict__ hcat) {
    int idx = blockIdx.x * 256 + threadIdx.x;
    if (idx >= BATCH * 128 * NPIX) return;
    int p = idx & 16383;
    int c = (idx >> 14) & 127;
    int b = idx >> 21;
    hcat[(b * 264 + c) * NPIX + p] = feat0[idx];
}

__global__ void hcat_tail_kernel(const float* __restrict__ flow, float* __restrict__ hcat) {
    int idx = blockIdx.x * 256 + threadIdx.x;
    if (idx >= BATCH * 8 * NPIX) return;
    int p = idx & 16383;
    int c2 = (idx >> 14) & 7;
    int b = idx / (8 * NPIX);
    float v = (c2 < 2) ? flow[(b * 2 + c2) * NPIX + p] : 0.f;
    hcat[(b * 264 + 256 + c2) * NPIX + p] = v;
}

// ---------------- host launch ----------------
extern "C" void kernel_launch(void* const* d_in, const int* in_sizes, int n_in,
                              void* d_out, int out_size)
{
    const float* feat0     = (const float*)d_in[0];
    const float* feat1     = (const float*)d_in[1];
    const float* flow_init = (const float*)d_in[2];
    const float* lc_w1 = (const float*)d_in[3];
    const float* lc_b1 = (const float*)d_in[4];
    const float* lc_w2 = (const float*)d_in[5];
    const float* lc_b2 = (const float*)d_in[6];
    const float* qw = (const float*)d_in[7];
    const float* qb = (const float*)d_in[8];
    const float* kw = (const float*)d_in[9];
    const float* kb = (const float*)d_in[10];
    const float* fr_w1 = (const float*)d_in[11];
    const float* fr_b1 = (const float*)d_in[12];
    const float* fr_w2 = (const float*)d_in[13];
    const float* fr_b2 = (const float*)d_in[14];
    const float* fr_w3 = (const float*)d_in[15];
    const float* fr_b3 = (const float*)d_in[16];
    const float* cf_w1 = (const float*)d_in[17];
    const float* cf_b1 = (const float*)d_in[18];
    const float* cf_w2 = (const float*)d_in[19];
    const float* cf_b2 = (const float*)d_in[20];
    const float* cf_w3 = (const float*)d_in[21];
    const float* cf_b3 = (const float*)d_in[22];
    float* out = (float*)d_out;

    float *p_lf0, *p_lf1, *p_lf0t, *p_lf1t, *p_tmp, *p_at, *p_gt, *p_alpha, *p_beta;
    float *p_flow, *p_fi, *p_hcat, *p_h2, *p_Mw, *p_uvc;
    cudaGetSymbolAddress((void**)&p_lf0,  g_lf0);
    cudaGetSymbolAddress((void**)&p_lf1,  g_lf1);
    cudaGetSymbolAddress((void**)&p_lf0t, g_lf0t);
    cudaGetSymbolAddress((void**)&p_lf1t, g_lf1t);
    cudaGetSymbolAddress((void**)&p_tmp,  g_tmp);
    cudaGetSymbolAddress((void**)&p_at,   g_at);
    cudaGetSymbolAddress((void**)&p_gt,   g_gt);
    cudaGetSymbolAddress((void**)&p_alpha,g_alpha);
    cudaGetSymbolAddress((void**)&p_beta, g_beta);
    cudaGetSymbolAddress((void**)&p_flow, g_flow);
    cudaGetSymbolAddress((void**)&p_fi,   g_fi);
    cudaGetSymbolAddress((void**)&p_hcat, g_hcat);
    cudaGetSymbolAddress((void**)&p_h2,   g_h2);
    cudaGetSymbolAddress((void**)&p_Mw,   g_Mw);
    cudaGetSymbolAddress((void**)&p_uvc,  g_uvc);

    dim3 cgrid(64, 8, BATCH);            // 16x16 tiles, 8 co-groups
    dim3 dgrid(64, 8, 2 * BATCH);        // dual: feat0/feat1 chains packed

    // local_conv on both features: two dual launches instead of four
    // (tmp0 = g_tmp, tmp1 = g_at reused as scratch pre-loop)
    conv3x3_dual_kernel<1><<<dgrid, 256>>>(feat0, feat1, lc_w1, lc_b1, p_tmp, p_at);
    conv3x3_dual_kernel<0><<<dgrid, 256>>>(p_tmp, p_at, lc_w2, lc_b2, p_lf0, p_lf1);

    // NHWC copies of lf0/lf1 (loop-invariant)
    transpose_kernel<<<dim3(512, 4, BATCH), 256>>>(p_lf0, p_lf0t);
    transpose_kernel<<<dim3(512, 4, BATCH), 256>>>(p_lf1, p_lf1t);

    // attention weight precomputation (once)
    prep_M_kernel<<<64, 256>>>(qw, kw, p_Mw);
    prep_uvc_kernel<<<1, 128>>>(qw, qb, kw, kb, p_uvc);

    copy_kernel<<<(BATCH * 2 * NPIX + 255) / 256, 256>>>(flow_init, p_flow, BATCH * 2 * NPIX);

    for (int it = 0; it < 10; it++) {
        warp_diff_t_kernel<<<4096, 256>>>(p_lf0t, p_lf1t, p_flow, p_uvc, p_at, p_alpha, p_beta);
        gemm_g_kernel<<<256, 256>>>(p_at, p_Mw, p_gt);
        attn_t_kernel<<<4096, 256>>>(p_at, p_gt, p_alpha, p_beta, p_uvc, p_flow, p_fi);
        fr_fused_kernel<<<dim3(128, BATCH), 256>>>(p_fi, fr_w1, fr_b1, fr_w2, fr_b2, fr_w3, fr_b3, p_flow);
    }

    // confidence head
    warp_feat_kernel<<<4096, 256>>>(feat1, p_flow, p_hcat);
    hcat_feat0_kernel<<<(BATCH * 128 * NPIX + 255) / 256, 256>>>(feat0, p_hcat);
    hcat_tail_kernel<<<(BATCH * 8 * NPIX + 255) / 256, 256>>>(p_flow, p_hcat);
    conv3x3_kernel<1><<<cgrid, 256>>>(p_hcat, cf_w1, cf_b1, p_tmp, 258, 264, 128);
    conv3x3_kernel<1><<<dim3(64, 4, BATCH), 256>>>(p_tmp, cf_w2, cf_b2, p_h2, 128, 128, 64);
    conv_small_kernel<64, 1, 2, false><<<(BATCH * NPIX + 255) / 256, 256>>>(p_h2, cf_w3, cf_b3, out + BATCH * 2 * NPIX);

    copy_kernel<<<(BATCH * 2 * NPIX + 255) / 256, 256>>>(p_flow, out, BATCH * 2 * NPIX);
}